// round 11
// baseline (speedup 1.0000x reference)
#include <cuda_runtime.h>

#define FULL_MASK 0xffffffffu

// softmax over 2 children collapses to sigmoid of the mean difference.
// exp-based form keeps RELATIVE precision for small probabilities.
__device__ __forceinline__ float fsigmoid(float x) {
    return __fdividef(1.0f, 1.0f + __expf(-x));
}

// padded SMEM index for the s8 transpose: conflict-free both directions
__device__ __forceinline__ int padidx(int L) { return L + (L >> 5); }

// 256-bit global load, L2 evict_last (input biased to stay L2-resident).
__device__ __forceinline__ void ldg256_evl(const float* p, float v[8]) {
    unsigned r0,r1,r2,r3,r4,r5,r6,r7;
    asm volatile("ld.global.nc.L2::evict_last.v8.b32 {%0,%1,%2,%3,%4,%5,%6,%7}, [%8];"
        : "=r"(r0),"=r"(r1),"=r"(r2),"=r"(r3),
          "=r"(r4),"=r"(r5),"=r"(r6),"=r"(r7) : "l"(p));
    v[0]=__uint_as_float(r0); v[1]=__uint_as_float(r1);
    v[2]=__uint_as_float(r2); v[3]=__uint_as_float(r3);
    v[4]=__uint_as_float(r4); v[5]=__uint_as_float(r5);
    v[6]=__uint_as_float(r6); v[7]=__uint_as_float(r7);
}
// 256-bit global store, L2 evict_first (output streams through L2).
__device__ __forceinline__ void stg256_evf(float* p, const float v[8]) {
    asm volatile("st.global.L2::evict_first.v8.b32 [%0], {%1,%2,%3,%4,%5,%6,%7,%8};"
        :: "l"(p),
           "r"(__float_as_uint(v[0])), "r"(__float_as_uint(v[1])),
           "r"(__float_as_uint(v[2])), "r"(__float_as_uint(v[3])),
           "r"(__float_as_uint(v[4])), "r"(__float_as_uint(v[5])),
           "r"(__float_as_uint(v[6])), "r"(__float_as_uint(v[7]))
        : "memory");
}

// One warp per row of 1024 floats, complete binary tree depth 10.
// Chunk M (0..127) = aligned 8-leaf block = a d=7 subtree.
// Phase A (coalesced, M = lane+32k): 256-bit load, stage ONLY the chunk
//   sums s8 (0.5KB/row) through padded SMEM to switch ownership.
// Phase B (lane t owns chunks 4t..4t+3): within-lane tree (d=5,6) +
//   5-step shfl butterfly (d=0..4); per-chunk path probs p8 staged back.
// Phase C (coalesced): RELOAD the input chunk (L1 hit — same lane, same
//   address, line still resident) and finish levels d=7,8,9 in registers.
//   No diff arrays cross phases -> tiny SMEM, low regs, high occupancy.
// Persistent grid-stride loop over rows removes wave quantization.
__global__ void __launch_bounds__(256, 6)
nbdt_kernel(const float* __restrict__ in, float* __restrict__ out, int nrows)
{
    __shared__ float s8s[8][132];          // s8 / p8 transpose (128 + pad)
    const int warp = threadIdx.x >> 5;
    const int lane = threadIdx.x & 31;
    const int wstride = gridDim.x << 3;

    for (int row = (blockIdx.x << 3) + warp; row < nrows; row += wstride) {
        const float* rin  = in  + (size_t)row * 1024;
        float*       rout = out + (size_t)row * 1024;

        // ---- Phase A: chunk sums only ----
        #pragma unroll
        for (int k = 0; k < 4; k++) {
            int M = lane + (k << 5);
            float v[8];
            ldg256_evl(rin + (M << 3), v);
            float a0 = v[0]+v[1], a1 = v[2]+v[3], a2 = v[4]+v[5], a3 = v[6]+v[7];
            s8s[warp][padidx(M)] = (a0 + a1) + (a2 + a3);
        }
        __syncwarp();

        // ---- Phase B: tree over chunk sums ----
        float s8[4];
        #pragma unroll
        for (int j = 0; j < 4; j++)
            s8[j] = s8s[warp][padidx((lane << 2) + j)];
        float s16[2] = { s8[0] + s8[1], s8[2] + s8[3] };
        float sum = s16[0] + s16[1];       // sum of my 32 leaves

        // cross-lane levels d=4..0: prob = sigmoid((my_sum - sib_sum)/blk)
        float acc = 1.0f;
        float inv = 1.0f / 32.0f;
        #pragma unroll
        for (int s = 0; s < 5; s++) {
            float part = __shfl_xor_sync(FULL_MASK, sum, 1 << s);
            acc *= fsigmoid((sum - part) * inv);
            sum += part;
            inv *= 0.5f;
        }

        // d=5 (16-leaf children)
        float p16[2];
        {
            float pl = fsigmoid((s16[0] - s16[1]) * (1.0f / 16.0f));
            float a = acc * pl;  p16[0] = a;  p16[1] = acc - a;
        }
        // d=6 (8-leaf children) -> per-chunk path prob p8, staged back.
        // Same-lane slots: no cross-lane sync needed before these writes.
        #pragma unroll
        for (int i = 0; i < 2; i++) {
            float pl = fsigmoid((s8[2*i] - s8[2*i+1]) * 0.125f);
            float a = p16[i] * pl;
            s8s[warp][padidx((lane << 2) + 2*i)]     = a;
            s8s[warp][padidx((lane << 2) + 2*i + 1)] = p16[i] - a;
        }
        __syncwarp();

        // ---- Phase C: reload (L1 hit) + finish d=7,8,9 ----
        #pragma unroll
        for (int k = 0; k < 4; k++) {
            int M = lane + (k << 5);
            float v[8];
            ldg256_evl(rin + (M << 3), v);
            float p  = s8s[warp][padidx(M)];
            float a0 = v[0]+v[1], a1 = v[2]+v[3], a2 = v[4]+v[5], a3 = v[6]+v[7];
            float b0 = a0 + a1,   b1 = a2 + a3;
            float pl7 = fsigmoid((b0 - b1) * 0.25f);
            float hi = p * pl7, lo = p - hi;
            float pa = fsigmoid((a0 - a1) * 0.5f);
            float q0 = hi * pa, q1 = hi - q0;
            float pb = fsigmoid((a2 - a3) * 0.5f);
            float q2 = lo * pb, q3 = lo - q2;
            float o[8];
            float t0 = fsigmoid(v[0]-v[1]); o[0] = q0 * t0; o[1] = q0 - o[0];
            float t1 = fsigmoid(v[2]-v[3]); o[2] = q1 * t1; o[3] = q1 - o[2];
            float t2 = fsigmoid(v[4]-v[5]); o[4] = q2 * t2; o[5] = q2 - o[4];
            float t3 = fsigmoid(v[6]-v[7]); o[6] = q3 * t3; o[7] = q3 - o[6];
            stg256_evf(rout + (M << 3), o);
        }
        __syncwarp();   // protect s8s before next iteration's Phase A
    }
}

extern "C" void kernel_launch(void* const* d_in, const int* in_sizes, int n_in,
                              void* d_out, int out_size)
{
    const float* in = (const float*)d_in[0];
    float* out = (float*)d_out;
    int rows = in_sizes[0] / 1024;             // BATCH = 16384
    int grid = 148 * 6;                        // persistent: one wave at occ 6
    if (grid * 8 > rows) grid = (rows + 7) / 8;
    nbdt_kernel<<<grid, 256>>>(in, out, rows);
}

// round 13
// speedup vs baseline: 1.6731x; 1.6731x over previous
#include <cuda_runtime.h>

#define FULL_MASK 0xffffffffu

// softmax over 2 children collapses to sigmoid of the mean difference.
__device__ __forceinline__ float fsigmoid(float x) {
    return __fdividef(1.0f, 1.0f + __expf(-x));
}

// padded SMEM index for the s8 transpose: conflict-free both directions
__device__ __forceinline__ int padidx(int L) { return L + (L >> 5); }

// 256-bit global load, L2 evict_last (input biased to stay L2-resident).
__device__ __forceinline__ void ldg256_evl(const float* p, float v[8]) {
    unsigned r0,r1,r2,r3,r4,r5,r6,r7;
    asm volatile("ld.global.nc.L2::evict_last.v8.b32 {%0,%1,%2,%3,%4,%5,%6,%7}, [%8];"
        : "=r"(r0),"=r"(r1),"=r"(r2),"=r"(r3),
          "=r"(r4),"=r"(r5),"=r"(r6),"=r"(r7) : "l"(p));
    v[0]=__uint_as_float(r0); v[1]=__uint_as_float(r1);
    v[2]=__uint_as_float(r2); v[3]=__uint_as_float(r3);
    v[4]=__uint_as_float(r4); v[5]=__uint_as_float(r5);
    v[6]=__uint_as_float(r6); v[7]=__uint_as_float(r7);
}
// 256-bit global store, L2 evict_first (output streams through L2).
__device__ __forceinline__ void stg256_evf(float* p, const float v[8]) {
    asm volatile("st.global.L2::evict_first.v8.b32 [%0], {%1,%2,%3,%4,%5,%6,%7,%8};"
        :: "l"(p),
           "r"(__float_as_uint(v[0])), "r"(__float_as_uint(v[1])),
           "r"(__float_as_uint(v[2])), "r"(__float_as_uint(v[3])),
           "r"(__float_as_uint(v[4])), "r"(__float_as_uint(v[5])),
           "r"(__float_as_uint(v[6])), "r"(__float_as_uint(v[7]))
        : "memory");
}

// One warp processes TWO rows of 1024 floats, interleaved for ILP: the two
// independent LDG->tree->sigmoid->STG chains overlap inside the warp, and
// the two __syncwarp()s are amortized across both rows.
// Per row (as in the best R8 kernel): chunk M (0..127) = 8 aligned leaves.
// Phase A (coalesced, M = lane+32k): 256-bit load; keep d7,d8 diffs in regs,
//   d9 diffs in per-warp SMEM; stage chunk sums s8 through padded SMEM.
// Phase B (lane t owns chunks 4t..4t+3 = leaves [32t,32t+32)): within-lane
//   tree (d=5,6) + 5-step shfl butterfly (d=0..4); path probs p8 staged back.
// Phase C (coalesced): finish levels d=7,8,9 and store 256-bit.
__global__ void __launch_bounds__(256, 3)
nbdt_kernel(const float* __restrict__ in, float* __restrict__ out)
{
    __shared__ float  s8s[16][132];    // per warp-row: s8 / p8 transpose
    __shared__ float4 d9s[16][128];    // per warp-row: leaf-pair diffs
    const int warp = threadIdx.x >> 5;
    const int lane = threadIdx.x & 31;
    const int row0 = (blockIdx.x << 4) + (warp << 1);   // rows row0, row0+1

    const float* rin[2]  = { in  + (size_t)row0 * 1024,
                             in  + (size_t)(row0 + 1) * 1024 };
    float*       rout[2] = { out + (size_t)row0 * 1024,
                             out + (size_t)(row0 + 1) * 1024 };
    const int slot[2] = { warp << 1, (warp << 1) + 1 };

    // ---- Phase A (both rows interleaved) ----
    float d7[2][4], d8[2][8];
    #pragma unroll
    for (int k = 0; k < 4; k++) {
        #pragma unroll
        for (int r = 0; r < 2; r++) {
            int M = lane + (k << 5);
            float v[8];
            ldg256_evl(rin[r] + (M << 3), v);
            float a0 = v[0]+v[1], a1 = v[2]+v[3], a2 = v[4]+v[5], a3 = v[6]+v[7];
            d9s[slot[r]][M] = make_float4(v[0]-v[1], v[2]-v[3], v[4]-v[5], v[6]-v[7]);
            float b0 = a0 + a1, b1 = a2 + a3;
            d8[r][2*k]   = a0 - a1;
            d8[r][2*k+1] = a2 - a3;
            d7[r][k] = b0 - b1;
            s8s[slot[r]][padidx(M)] = b0 + b1;
        }
    }
    __syncwarp();

    // ---- Phase B (both rows interleaved) ----
    #pragma unroll
    for (int r = 0; r < 2; r++) {
        float s8[4];
        #pragma unroll
        for (int j = 0; j < 4; j++)
            s8[j] = s8s[slot[r]][padidx((lane << 2) + j)];
        float s16[2] = { s8[0] + s8[1], s8[2] + s8[3] };
        float sum = s16[0] + s16[1];       // sum of my 32 leaves

        // cross-lane levels d=4..0: prob = sigmoid((my_sum - sib_sum)/blk)
        float acc = 1.0f;
        float inv = 1.0f / 32.0f;
        #pragma unroll
        for (int s = 0; s < 5; s++) {
            float part = __shfl_xor_sync(FULL_MASK, sum, 1 << s);
            acc *= fsigmoid((sum - part) * inv);
            sum += part;
            inv *= 0.5f;
        }

        // d=5 (16-leaf children)
        float p16[2];
        {
            float pl = fsigmoid((s16[0] - s16[1]) * (1.0f / 16.0f));
            float a = acc * pl;  p16[0] = a;  p16[1] = acc - a;
        }
        // d=6 (8-leaf children) -> per-chunk path prob p8, staged back.
        // Same-lane slots: no cross-lane sync needed before these writes.
        #pragma unroll
        for (int i = 0; i < 2; i++) {
            float pl = fsigmoid((s8[2*i] - s8[2*i+1]) * 0.125f);
            float a = p16[i] * pl;
            s8s[slot[r]][padidx((lane << 2) + 2*i)]     = a;
            s8s[slot[r]][padidx((lane << 2) + 2*i + 1)] = p16[i] - a;
        }
    }
    __syncwarp();

    // ---- Phase C (both rows interleaved) ----
    #pragma unroll
    for (int k = 0; k < 4; k++) {
        #pragma unroll
        for (int r = 0; r < 2; r++) {
            int M = lane + (k << 5);
            float p   = s8s[slot[r]][padidx(M)];
            float pl7 = fsigmoid(d7[r][k] * 0.25f);
            float hi = p * pl7, lo = p - hi;
            float pa = fsigmoid(d8[r][2*k] * 0.5f);
            float q0 = hi * pa, q1 = hi - q0;
            float pb = fsigmoid(d8[r][2*k+1] * 0.5f);
            float q2 = lo * pb, q3 = lo - q2;
            float4 d9 = d9s[slot[r]][M];
            float o[8];
            float t0 = fsigmoid(d9.x); o[0] = q0 * t0; o[1] = q0 - o[0];
            float t1 = fsigmoid(d9.y); o[2] = q1 * t1; o[3] = q1 - o[2];
            float t2 = fsigmoid(d9.z); o[4] = q2 * t2; o[5] = q2 - o[4];
            float t3 = fsigmoid(d9.w); o[6] = q3 * t3; o[7] = q3 - o[6];
            stg256_evf(rout[r] + (M << 3), o);
        }
    }
}

extern "C" void kernel_launch(void* const* d_in, const int* in_sizes, int n_in,
                              void* d_out, int out_size)
{
    const float* in = (const float*)d_in[0];
    float* out = (float*)d_out;
    int rows = in_sizes[0] / 1024;             // BATCH = 16384
    nbdt_kernel<<<rows / 16, 256>>>(in, out);  // 16 rows per block (2/warp)
}